// round 3
// baseline (speedup 1.0000x reference)
#include <cuda_runtime.h>
#include <cuda_bf16.h>

// SplineActivation: y[b][d] = sum_k Bspline_k(x[b][d]) * coeffs[d][k]
// Uniform cubic B-spline. Per (dim, interval j) the result is a cubic in the
// local parameter u: y = ((A u + B) u + C) u + D, with (A,B,C,D) fixed linear
// combos of coeffs[d][j..j+3]/6. Each block precomputes the (A,B,C,D) table
// for its 512 dims into shared memory (padded stride 5 float4/dim for
// near-conflict-free LDS.128), then the streaming loop is:
//   t = 2x+2; j = (int)t; u = t-j; h = tab[dim*5+j]; 3 FMAs.

#define INPUT_DIM 4096
#define BATCH_N   4096
#define ROWS_PER  16
#define TPB       128
#define DIMS_PB   (TPB * 4)          // 512 dims per block

__global__ void __launch_bounds__(TPB)
spline_activation_kernel(const float4* __restrict__ x,
                         const float4* __restrict__ coeffs4,
                         float4* __restrict__ out) {
    // [dimLocal*5 + j] float4 entries; slot 4 of each dim is padding.
    __shared__ float4 tab[DIMS_PB * 5];      // 40960 B

    const int DQ = INPUT_DIM / 4;            // 1024 float4 columns
    int tid = threadIdx.x;
    int dq  = blockIdx.x * TPB + tid;        // global column-quad

    // ---- Build phase: Horner table for this thread's 4 dims ----
    {
        const float k6 = 1.0f / 6.0f;
        float c[28];
        const float4* cp = coeffs4 + (size_t)dq * 7;   // 28 floats, 16B aligned
#pragma unroll
        for (int i = 0; i < 7; ++i) {
            float4 v = __ldg(cp + i);
            c[4 * i + 0] = v.x * k6;
            c[4 * i + 1] = v.y * k6;
            c[4 * i + 2] = v.z * k6;
            c[4 * i + 3] = v.w * k6;
        }
#pragma unroll
        for (int d = 0; d < 4; ++d) {
            const float* e = c + 7 * d;
#pragma unroll
            for (int j = 0; j < 4; ++j) {
                float e0 = e[j], e1 = e[j + 1], e2 = e[j + 2], e3 = e[j + 3];
                float4 h;
                h.x = fmaf(3.0f, e1 - e2, e3 - e0);          // A
                h.y = fmaf(-6.0f, e1, 3.0f * (e0 + e2));     // B
                h.z = 3.0f * (e2 - e0);                      // C
                h.w = fmaf(4.0f, e1, e0 + e2);               // D
                tab[(tid * 4 + d) * 5 + j] = h;
            }
        }
    }
    __syncthreads();

    // Per-component table bases (hoisted address math).
    const float4* t0 = tab + (tid * 4 + 0) * 5;
    const float4* t1 = tab + (tid * 4 + 1) * 5;
    const float4* t2 = tab + (tid * 4 + 2) * 5;
    const float4* t3 = tab + (tid * 4 + 3) * 5;

    int brow0 = blockIdx.y * ROWS_PER;

#pragma unroll 4
    for (int r = 0; r < ROWS_PER; ++r) {
        size_t idx = (size_t)(brow0 + r) * DQ + dq;
        float4 xv = __ldg(x + idx);
        float4 ov;
        {
            float t = fmaf(xv.x, 2.0f, 2.0f);
            int j = (int)t;                  // t in [0,4): trunc == floor
            float u = t - (float)j;
            float4 h = t0[j];
            ov.x = fmaf(fmaf(fmaf(h.x, u, h.y), u, h.z), u, h.w);
        }
        {
            float t = fmaf(xv.y, 2.0f, 2.0f);
            int j = (int)t;
            float u = t - (float)j;
            float4 h = t1[j];
            ov.y = fmaf(fmaf(fmaf(h.x, u, h.y), u, h.z), u, h.w);
        }
        {
            float t = fmaf(xv.z, 2.0f, 2.0f);
            int j = (int)t;
            float u = t - (float)j;
            float4 h = t2[j];
            ov.z = fmaf(fmaf(fmaf(h.x, u, h.y), u, h.z), u, h.w);
        }
        {
            float t = fmaf(xv.w, 2.0f, 2.0f);
            int j = (int)t;
            float u = t - (float)j;
            float4 h = t3[j];
            ov.w = fmaf(fmaf(fmaf(h.x, u, h.y), u, h.z), u, h.w);
        }
        out[idx] = ov;
    }
}

extern "C" void kernel_launch(void* const* d_in, const int* in_sizes, int n_in,
                              void* d_out, int out_size) {
    const float4* x      = (const float4*)d_in[0];   // (4096, 4096) fp32
    const float4* coeffs = (const float4*)d_in[1];   // (4096, 7) fp32
    float4*       out    = (float4*)d_out;           // (4096, 4096) fp32

    dim3 grid((INPUT_DIM / 4) / TPB, BATCH_N / ROWS_PER, 1);  // (8, 256)
    spline_activation_kernel<<<grid, TPB>>>(x, coeffs, out);
}

// round 4
// speedup vs baseline: 1.5222x; 1.5222x over previous
#include <cuda_runtime.h>
#include <cuda_bf16.h>

// SplineActivation: y[b][d] = sum_k Bspline_k(x[b][d]) * coeffs[d][k]
// Uniform cubic B-spline. Branch-free truncated-power form: with t = 2x+2 in
// [0,4) and P_j the piece-j cubic (in t), C^2 continuity gives exactly
//   y(t) = P_0(t) + sum_{k=1..3} alpha_k * (t-k)_+^3,
//   alpha_k = A_k - A_{k-1}  (jump of the leading cubic coefficient).
// With p = (t-k) + |t-k| = 2*(t-k)_+ and beta = alpha/8:
//   y = Horner(P_0, t) + sum beta_k * p_k^3.
// No predicates, no selects, no int<->float converts: 19 fp ops per element.

#define INPUT_DIM 4096
#define BATCH_N   4096
#define ROWS_PER  8
#define TPB       128

struct DimPoly { float A, B, C, D, b1, b2, b3; };

__device__ __forceinline__ float eval_dim(float xv, const DimPoly& q) {
    float t = fmaf(xv, 2.0f, 2.0f);                        // [0, 4)
    // independent ReLU-cube terms (good ILP vs the Horner chain)
    float r1 = t - 1.0f, r2 = t - 2.0f, r3 = t - 3.0f;
    float p1 = r1 + fabsf(r1);                             // 2*(t-1)_+
    float p2 = r2 + fabsf(r2);
    float p3 = r3 + fabsf(r3);
    float h = fmaf(fmaf(fmaf(q.A, t, q.B), t, q.C), t, q.D);
    h = fmaf(q.b1 * p1, p1 * p1, h);
    h = fmaf(q.b2 * p2, p2 * p2, h);
    h = fmaf(q.b3 * p3, p3 * p3, h);
    return h;
}

__device__ __forceinline__ float lead_coef(const float* e) {
    // A_j = 3*(e1-e2) + (e3-e0), leading cubic coefficient of window j
    return fmaf(3.0f, e[1] - e[2], e[3] - e[0]);
}

__global__ void __launch_bounds__(TPB)
spline_activation_kernel(const float4* __restrict__ x,
                         const float4* __restrict__ coeffs4,
                         float4* __restrict__ out) {
    const int DQ = INPUT_DIM / 4;                   // 1024 float4 columns
    int dq = blockIdx.x * TPB + threadIdx.x;        // column-quad index

    // Load 28 coeffs (4 dims x 7) as 7 x LDG.128, scale by 1/6, build per-dim
    // truncated-power parameters in registers.
    const float k6 = 1.0f / 6.0f;
    float c[28];
    const float4* cp = coeffs4 + (size_t)dq * 7;
#pragma unroll
    for (int i = 0; i < 7; ++i) {
        float4 v = __ldg(cp + i);
        c[4 * i + 0] = v.x * k6;
        c[4 * i + 1] = v.y * k6;
        c[4 * i + 2] = v.z * k6;
        c[4 * i + 3] = v.w * k6;
    }

    DimPoly q[4];
#pragma unroll
    for (int d = 0; d < 4; ++d) {
        const float* e = c + 7 * d;
        float A0 = lead_coef(e + 0);
        float A1 = lead_coef(e + 1);
        float A2 = lead_coef(e + 2);
        float A3 = lead_coef(e + 3);
        q[d].A  = A0;
        q[d].B  = fmaf(-6.0f, e[1], 3.0f * (e[0] + e[2]));
        q[d].C  = 3.0f * (e[2] - e[0]);
        q[d].D  = fmaf(4.0f, e[1], e[0] + e[2]);
        q[d].b1 = (A1 - A0) * 0.125f;
        q[d].b2 = (A2 - A1) * 0.125f;
        q[d].b3 = (A3 - A2) * 0.125f;
    }

    int brow0 = blockIdx.y * ROWS_PER;

#pragma unroll
    for (int r = 0; r < ROWS_PER; ++r) {
        size_t idx = (size_t)(brow0 + r) * DQ + dq;
        float4 xv = __ldg(x + idx);
        float4 ov;
        ov.x = eval_dim(xv.x, q[0]);
        ov.y = eval_dim(xv.y, q[1]);
        ov.z = eval_dim(xv.z, q[2]);
        ov.w = eval_dim(xv.w, q[3]);
        out[idx] = ov;
    }
}

extern "C" void kernel_launch(void* const* d_in, const int* in_sizes, int n_in,
                              void* d_out, int out_size) {
    const float4* x      = (const float4*)d_in[0];   // (4096, 4096) fp32
    const float4* coeffs = (const float4*)d_in[1];   // (4096, 7) fp32
    float4*       out    = (float4*)d_out;           // (4096, 4096) fp32

    dim3 grid((INPUT_DIM / 4) / TPB, BATCH_N / ROWS_PER, 1);  // (8, 512)
    spline_activation_kernel<<<grid, TPB>>>(x, coeffs, out);
}

// round 5
// speedup vs baseline: 1.5347x; 1.0082x over previous
#include <cuda_runtime.h>
#include <cuda_bf16.h>
#include <cstdint>

// SplineActivation: y[b][d] = sum_k Bspline_k(x[b][d]) * coeffs[d][k]
// Uniform cubic B-spline, branch-free truncated-power form (see R4):
//   y(t) = P_0(t) + sum_{k=1..3} beta_k * p_k^3,  p_k = (t-k)+|t-k|, t = 2x+2
// evaluated with Blackwell packed f32x2 FMA: two dims per instruction.
// ptxas never auto-fuses f32x2 — emitted via inline PTX.

#define INPUT_DIM 4096
#define BATCH_N   4096
#define ROWS_PER  8
#define TPB       128

typedef unsigned long long u64;

__device__ __forceinline__ u64 pack2(float lo, float hi) {
    u64 r; asm("mov.b64 %0, {%1, %2};" : "=l"(r) : "f"(lo), "f"(hi)); return r;
}
__device__ __forceinline__ u64 fma2(u64 a, u64 b, u64 c) {
    u64 d; asm("fma.rn.f32x2 %0, %1, %2, %3;" : "=l"(d) : "l"(a), "l"(b), "l"(c)); return d;
}
__device__ __forceinline__ u64 mul2(u64 a, u64 b) {
    u64 d; asm("mul.rn.f32x2 %0, %1, %2;" : "=l"(d) : "l"(a), "l"(b)); return d;
}
__device__ __forceinline__ u64 add2(u64 a, u64 b) {
    u64 d; asm("add.rn.f32x2 %0, %1, %2;" : "=l"(d) : "l"(a), "l"(b)); return d;
}
__device__ __forceinline__ u64 abs2(u64 a) { return a & 0x7FFFFFFF7FFFFFFFULL; }

struct PairPoly { u64 A, B, C, D, b1, b2, b3; };   // per dim-pair, lanes = dims

__device__ __forceinline__ u64 eval_pair(u64 x2, const PairPoly& q,
                                         u64 two2, u64 one2, u64 n1_2) {
    // t = 2x+2; r_k = t-k computed independently: r1=2x+1, r2=2x, r3=2x-1
    u64 t  = fma2(x2, two2, two2);
    u64 r1 = fma2(x2, two2, one2);
    u64 r2 = mul2(x2, two2);
    u64 r3 = fma2(x2, two2, n1_2);
    u64 p1 = add2(r1, abs2(r1));          // 2*(t-1)_+
    u64 p2 = add2(r2, abs2(r2));
    u64 p3 = add2(r3, abs2(r3));
    u64 h  = fma2(fma2(fma2(q.A, t, q.B), t, q.C), t, q.D);
    h = fma2(mul2(q.b1, p1), mul2(p1, p1), h);
    h = fma2(mul2(q.b2, p2), mul2(p2, p2), h);
    h = fma2(mul2(q.b3, p3), mul2(p3, p3), h);
    return h;
}

__device__ __forceinline__ float lead_coef(const float* e) {
    return fmaf(3.0f, e[1] - e[2], e[3] - e[0]);   // leading cubic coeff of window
}

struct DimPoly { float A, B, C, D, b1, b2, b3; };

__device__ __forceinline__ DimPoly build_dim(const float* e) {
    DimPoly q;
    float A0 = lead_coef(e + 0), A1 = lead_coef(e + 1);
    float A2 = lead_coef(e + 2), A3 = lead_coef(e + 3);
    q.A  = A0;
    q.B  = fmaf(-6.0f, e[1], 3.0f * (e[0] + e[2]));
    q.C  = 3.0f * (e[2] - e[0]);
    q.D  = fmaf(4.0f, e[1], e[0] + e[2]);
    q.b1 = (A1 - A0) * 0.125f;
    q.b2 = (A2 - A1) * 0.125f;
    q.b3 = (A3 - A2) * 0.125f;
    return q;
}

__global__ void __launch_bounds__(TPB)
spline_activation_kernel(const ulonglong2* __restrict__ x,
                         const float4* __restrict__ coeffs4,
                         ulonglong2* __restrict__ out) {
    const int DQ = INPUT_DIM / 4;                   // 1024 float4 columns
    int dq = blockIdx.x * TPB + threadIdx.x;        // column-quad index

    // Load 28 coeffs (4 dims x 7) as 7 x LDG.128, scale by 1/6.
    const float k6 = 1.0f / 6.0f;
    float c[28];
    const float4* cp = coeffs4 + (size_t)dq * 7;
#pragma unroll
    for (int i = 0; i < 7; ++i) {
        float4 v = __ldg(cp + i);
        c[4 * i + 0] = v.x * k6;
        c[4 * i + 1] = v.y * k6;
        c[4 * i + 2] = v.z * k6;
        c[4 * i + 3] = v.w * k6;
    }

    DimPoly s0 = build_dim(c + 0),  s1 = build_dim(c + 7);
    DimPoly s2 = build_dim(c + 14), s3 = build_dim(c + 21);

    PairPoly q01, q23;
    q01.A = pack2(s0.A, s1.A);   q23.A = pack2(s2.A, s3.A);
    q01.B = pack2(s0.B, s1.B);   q23.B = pack2(s2.B, s3.B);
    q01.C = pack2(s0.C, s1.C);   q23.C = pack2(s2.C, s3.C);
    q01.D = pack2(s0.D, s1.D);   q23.D = pack2(s2.D, s3.D);
    q01.b1 = pack2(s0.b1, s1.b1); q23.b1 = pack2(s2.b1, s3.b1);
    q01.b2 = pack2(s0.b2, s1.b2); q23.b2 = pack2(s2.b2, s3.b2);
    q01.b3 = pack2(s0.b3, s1.b3); q23.b3 = pack2(s2.b3, s3.b3);

    const u64 two2 = pack2(2.0f, 2.0f);
    const u64 one2 = pack2(1.0f, 1.0f);
    const u64 n1_2 = pack2(-1.0f, -1.0f);

    int brow0 = blockIdx.y * ROWS_PER;

#pragma unroll
    for (int r = 0; r < ROWS_PER; ++r) {
        size_t idx = (size_t)(brow0 + r) * DQ + dq;
        ulonglong2 xv = __ldg(x + idx);
        ulonglong2 ov;
        ov.x = eval_pair(xv.x, q01, two2, one2, n1_2);
        ov.y = eval_pair(xv.y, q23, two2, one2, n1_2);
        out[idx] = ov;
    }
}

extern "C" void kernel_launch(void* const* d_in, const int* in_sizes, int n_in,
                              void* d_out, int out_size) {
    const ulonglong2* x      = (const ulonglong2*)d_in[0];  // (4096, 4096) fp32
    const float4*     coeffs = (const float4*)d_in[1];      // (4096, 7) fp32
    ulonglong2*       out    = (ulonglong2*)d_out;          // (4096, 4096) fp32

    dim3 grid((INPUT_DIM / 4) / TPB, BATCH_N / ROWS_PER, 1);  // (8, 512)
    spline_activation_kernel<<<grid, TPB>>>(x, coeffs, out);
}